// round 7
// baseline (speedup 1.0000x reference)
#include <cuda_runtime.h>
#include <cuda.h>
#include <cuda_fp16.h>
#include <math.h>
#include <stdint.h>

#define Bsz   8
#define Tlen  2048
#define Cdim  1024
#define Edim  4096
#define Mtot  (Bsz * Tlen)       // 16384 tokens
#define CHUNK 32
#define NCHUNK (Tlen / CHUNK)    // 64

typedef __half f16;

// ---------------- scratch (no cudaMalloc allowed) ----------------
__device__ __align__(16) f16   g_y   [(size_t)Mtot * Cdim];   // rmsnorm1 out (fp16)
__device__ __align__(16) float g_out1[(size_t)Mtot * Cdim];   // gate*x (fp32, residual)
__device__ __align__(16) float g_csum[Bsz * NCHUNK * Cdim];

__device__ __align__(16) f16 g_s  [(size_t)Mtot * Cdim];   // state (fp16)
__device__ __align__(16) f16 g_h  [(size_t)Mtot * Cdim];   // rmsnorm2 out (fp16)
__device__ __align__(16) f16 g_act[(size_t)Mtot * Edim];   // relu hidden (fp16)

// transposed weights: [N, K] K-major fp16
__device__ __align__(16) f16 g_w1T [Cdim * Cdim];
__device__ __align__(16) f16 g_w2aT[(size_t)Edim * Cdim];
__device__ __align__(16) f16 g_w2bT[(size_t)Cdim * Edim];

// ---------------- helpers ----------------
__device__ __forceinline__ uint32_t smem_u32(const void* p) {
    uint32_t a;
    asm("{ .reg .u64 t; cvta.to.shared.u64 t, %1; cvt.u32.u64 %0, t; }" : "=r"(a) : "l"(p));
    return a;
}
__device__ __forceinline__ void cp16(uint32_t s, const void* g) {
    asm volatile("cp.async.cg.shared.global [%0], [%1], 16;" :: "r"(s), "l"(g) : "memory");
}
#define CP_COMMIT() asm volatile("cp.async.commit_group;" ::: "memory")
#define CP_WAIT(n)  asm volatile("cp.async.wait_group %0;" :: "n"(n) : "memory")

#define LDSM_X4(r, addr) \
    asm volatile("ldmatrix.sync.aligned.m8n8.x4.shared.b16 {%0,%1,%2,%3}, [%4];" \
        : "=r"((r)[0]), "=r"((r)[1]), "=r"((r)[2]), "=r"((r)[3]) : "r"(addr))

#define MMA_F16(d, a, b0, b1) \
    asm volatile("mma.sync.aligned.m16n8k16.row.col.f32.f16.f16.f32 " \
        "{%0,%1,%2,%3}, {%4,%5,%6,%7}, {%8,%9}, {%0,%1,%2,%3};" \
        : "+f"((d)[0]), "+f"((d)[1]), "+f"((d)[2]), "+f"((d)[3]) \
        : "r"((a)[0]), "r"((a)[1]), "r"((a)[2]), "r"((a)[3]), "r"(b0), "r"(b1))

// ---------------- fused prep: rmsnorm1 (fp16 out) + 3 weight transposes ----------------
__device__ __forceinline__ void rmsnorm_row_h(const float* __restrict__ x,
                                              const float* __restrict__ w,
                                              f16* __restrict__ y,
                                              int row, float* sh)
{
    const float4* xr = reinterpret_cast<const float4*>(x) + (size_t)row * (Cdim / 4);
    float4 v = xr[threadIdx.x];
    float ss = v.x * v.x + v.y * v.y + v.z * v.z + v.w * v.w;
    #pragma unroll
    for (int o = 16; o; o >>= 1) ss += __shfl_xor_sync(0xffffffffu, ss, o);
    int wid = threadIdx.x >> 5, lid = threadIdx.x & 31;
    if (lid == 0) sh[wid] = ss;
    __syncthreads();
    if (threadIdx.x < 8) {
        float t = sh[threadIdx.x];
        t += __shfl_xor_sync(0xffu, t, 1);
        t += __shfl_xor_sync(0xffu, t, 2);
        t += __shfl_xor_sync(0xffu, t, 4);
        if (threadIdx.x == 0) sh[0] = t;
    }
    __syncthreads();
    float inv = rsqrtf(sh[0] * (1.0f / Cdim) + 1e-6f);
    float4 wv = reinterpret_cast<const float4*>(w)[threadIdx.x];
    __half2 p0, p1;
    p0.x = __float2half(v.x * inv * wv.x);
    p0.y = __float2half(v.y * inv * wv.y);
    p1.x = __float2half(v.z * inv * wv.z);
    p1.y = __float2half(v.w * inv * wv.w);
    size_t base = (size_t)row * Cdim + threadIdx.x * 4;
    *reinterpret_cast<__half2*>(y + base)     = p0;
    *reinterpret_cast<__half2*>(y + base + 2) = p1;
}

__device__ __forceinline__ void transpose_tile(const float* __restrict__ in,
                                               f16* __restrict__ o16,
                                               int K, int N, int bx, int by, float* sh)
{
    int k0 = bx * 32, n0 = by * 32;
    int x = threadIdx.x & 31, y = threadIdx.x >> 5;
    #pragma unroll
    for (int i = y; i < 32; i += 8)
        sh[i * 33 + x] = in[(size_t)(k0 + i) * N + n0 + x];
    __syncthreads();
    #pragma unroll
    for (int i = y; i < 32; i += 8)
        o16[(size_t)(n0 + i) * K + k0 + x] = __float2half(sh[x * 33 + i]);
}

#define TW1  (Cdim / 32) * (Cdim / 32)   // 1024
#define TW2A (Cdim / 32) * (Edim / 32)   // 4096
#define TW2B (Edim / 32) * (Cdim / 32)   // 4096

__global__ void __launch_bounds__(256) prep_kernel(const float* __restrict__ x,
                                                   const float* __restrict__ n1w,
                                                   const float* __restrict__ w1,
                                                   const float* __restrict__ w2a,
                                                   const float* __restrict__ w2b)
{
    __shared__ float sh[32 * 33];
    int bid = blockIdx.x;
    if (bid < Mtot) { rmsnorm_row_h(x, n1w, g_y, bid, sh); return; }
    bid -= Mtot;
    if (bid < TW1)  { transpose_tile(w1,  g_w1T,  Cdim, Cdim, bid & 31, bid >> 5, sh); return; }
    bid -= TW1;
    if (bid < TW2A) { transpose_tile(w2a, g_w2aT, Cdim, Edim, bid & 31, bid >> 5, sh); return; }
    bid -= TW2A;
    transpose_tile(w2b, g_w2bT, Edim, Cdim, bid & 127, bid >> 7, sh);
}

// ---------------- standalone rmsnorm -> fp16 (h = rmsnorm(out1)) ----------------
__global__ void __launch_bounds__(256) rmsnorm_h_kernel(const float* __restrict__ x,
                                                        const float* __restrict__ w,
                                                        f16* __restrict__ yH)
{
    __shared__ float sh[8];
    int row = blockIdx.x;
    const float4* xr = reinterpret_cast<const float4*>(x) + (size_t)row * (Cdim / 4);
    float4 v = xr[threadIdx.x];
    float ss = v.x * v.x + v.y * v.y + v.z * v.z + v.w * v.w;
    #pragma unroll
    for (int o = 16; o; o >>= 1) ss += __shfl_xor_sync(0xffffffffu, ss, o);
    int wid = threadIdx.x >> 5, lid = threadIdx.x & 31;
    if (lid == 0) sh[wid] = ss;
    __syncthreads();
    if (threadIdx.x < 8) {
        float t = sh[threadIdx.x];
        t += __shfl_xor_sync(0xffu, t, 1);
        t += __shfl_xor_sync(0xffu, t, 2);
        t += __shfl_xor_sync(0xffu, t, 4);
        if (threadIdx.x == 0) sh[0] = t;
    }
    __syncthreads();
    float inv = rsqrtf(sh[0] * (1.0f / Cdim) + 1e-6f);
    float4 wv = reinterpret_cast<const float4*>(w)[threadIdx.x];
    size_t base = (size_t)row * Cdim + threadIdx.x * 4;
    __half2 p0, p1;
    p0.x = __float2half(v.x * inv * wv.x);
    p0.y = __float2half(v.y * inv * wv.y);
    p1.x = __float2half(v.z * inv * wv.z);
    p1.y = __float2half(v.w * inv * wv.w);
    *reinterpret_cast<__half2*>(yH + base)     = p0;
    *reinterpret_cast<__half2*>(yH + base + 2) = p1;
}

// ---------------- chunked scan (fp16 input, fp32 accumulate, 2 channels/thread) ----------------
#define C2 (Cdim / 2)

__global__ void __launch_bounds__(256) scan_partial()
{
    int b = blockIdx.x, ch = blockIdx.y;
    int c2 = blockIdx.z * 256 + threadIdx.x;
    const __half2* p = reinterpret_cast<const __half2*>(g_y)
                     + (size_t)(b * Tlen + ch * CHUNK) * C2 + c2;
    float2 s = make_float2(0.f, 0.f);
    #pragma unroll
    for (int t = 0; t < CHUNK; t++) {
        float2 v = __half22float2(p[(size_t)t * C2]);
        s.x += v.x; s.y += v.y;
    }
    reinterpret_cast<float2*>(g_csum)[(b * NCHUNK + ch) * C2 + c2] = s;
}

__global__ void __launch_bounds__(256) scan_prefix()
{
    int b = blockIdx.x;
    int c2 = blockIdx.y * 256 + threadIdx.x;
    float2* buf = reinterpret_cast<float2*>(g_csum);
    float2 run = make_float2(0.f, 0.f);
    #pragma unroll
    for (int ch = 0; ch < NCHUNK; ch++) {
        int idx = (b * NCHUNK + ch) * C2 + c2;
        float2 v = buf[idx];
        buf[idx] = run;
        run.x += v.x; run.y += v.y;
    }
}

__global__ void __launch_bounds__(256) scan_final()
{
    int b = blockIdx.x, ch = blockIdx.y;
    int c2 = blockIdx.z * 256 + threadIdx.x;
    float2 run = reinterpret_cast<const float2*>(g_csum)[(b * NCHUNK + ch) * C2 + c2];
    const __half2* p = reinterpret_cast<const __half2*>(g_y)
                     + (size_t)(b * Tlen + ch * CHUNK) * C2 + c2;
    __half2* o = reinterpret_cast<__half2*>(g_s)
               + (size_t)(b * Tlen + ch * CHUNK) * C2 + c2;
    int tg0 = ch * CHUNK;
    #pragma unroll
    for (int t = 0; t < CHUNK; t++) {
        float2 v = __half22float2(p[(size_t)t * C2]);
        run.x += v.x; run.y += v.y;
        float tg = (float)(tg0 + t);
        float rs = 1.0f / (0.5f * (tg + 1.f) * (tg + 2.f));
        __half2 hv;
        hv.x = __float2half(run.x * rs);
        hv.y = __float2half(run.y * rs);
        o[(size_t)t * C2] = hv;
    }
}

// ---------------- fp16 HMMA GEMM: 256x128x64 tiles, 3-stage cp.async, 512 thr ----------------
// A: [M,K] row-major f16, B: [N,K] row-major f16 -> C[M,N]
// EPI 0: outF = sigmoid(acc+bias) * aux
// EPI 1: outH = (f16) relu(acc+bias)
// EPI 2: outF = acc + bias + aux
#define BMt    256
#define BNt    128
#define BKt    64
#define STG    3
#define TILEA  32768                // 256 rows * 128B
#define TILEBB 16384                // 128 rows * 128B
#define TILEST (TILEA + TILEBB)     // 48KB per stage
#define SMTOT  (STG * TILEST)       // 144KB

__device__ __forceinline__ void load_tile64(const f16* __restrict__ A,
                                            const f16* __restrict__ B,
                                            int bm, int bn, int koff, int K,
                                            uint32_t sbase, int stage, int tid)
{
    uint32_t sA = sbase + stage * TILEST;
    uint32_t sB = sA + TILEA;
    #pragma unroll
    for (int i = 0; i < 4; i++) {
        int idx = tid + i * 512;          // 0..2047 (256 rows x 8 chunks)
        int row = idx >> 3, ch = idx & 7;
        int chs = ch ^ (row & 7);         // 128B-row swizzle
        uint32_t so = (uint32_t)(row * 128 + chs * 16);
        cp16(sA + so, A + (size_t)(bm + row) * K + koff + ch * 8);
    }
    #pragma unroll
    for (int i = 0; i < 2; i++) {
        int idx = tid + i * 512;          // 0..1023 (128 rows x 8 chunks)
        int row = idx >> 3, ch = idx & 7;
        int chs = ch ^ (row & 7);
        uint32_t so = (uint32_t)(row * 128 + chs * 16);
        cp16(sB + so, B + (size_t)(bn + row) * K + koff + ch * 8);
    }
}

template<int EPI>
__global__ void __launch_bounds__(512, 1) mma_gemm(
    const f16* __restrict__ Ag, const f16* __restrict__ Bg,
    const float* __restrict__ bias, const float* __restrict__ aux,
    float* __restrict__ outF, f16* __restrict__ outH,
    int N, int K)
{
    extern __shared__ __align__(16) char smem[];
    uint32_t sbase = smem_u32(smem);
    int tid = threadIdx.x, wid = tid >> 5, lane = tid & 31;
    int bm = blockIdx.y * BMt, bn = blockIdx.x * BNt;
    int wm = (wid >> 2) * 64, wn = (wid & 3) * 32;   // 4x4 warps, warp tile 64x32

    int nkt = K / BKt;

    float acc[4][4][4] = {};

    // prologue: prefetch 2 tiles
    load_tile64(Ag, Bg, bm, bn, 0,   K, sbase, 0, tid); CP_COMMIT();
    load_tile64(Ag, Bg, bm, bn, BKt, K, sbase, 1, tid); CP_COMMIT();

    // ldmatrix lane constants
    int l8 = lane & 7;
    int aRow  = wm + l8 + ((lane >> 3) & 1) * 8;   // + mf*16
    int aCHi  = (lane >> 4) & 1;
    int aXor  = aRow & 7;
    int bRow  = wn + l8 + ((lane >> 4) & 1) * 8;   // + g*16
    int bCHi  = (lane >> 3) & 1;
    int bXor  = bRow & 7;

    int cs = 0, ls = 2;   // compute stage, load stage
    for (int kk = 0; kk < nkt; kk++) {
        if (kk + 1 < nkt) { CP_WAIT(1); } else { CP_WAIT(0); }
        __syncthreads();

        if (kk + 2 < nkt) {
            load_tile64(Ag, Bg, bm, bn, (kk + 2) * BKt, K, sbase, ls, tid);
            CP_COMMIT();
            if (++ls == STG) ls = 0;
        }

        uint32_t sA = sbase + cs * TILEST;
        uint32_t sB = sA + TILEA;
        if (++cs == STG) cs = 0;

        #pragma unroll
        for (int ks = 0; ks < 4; ks++) {
            uint32_t a[4][4];
            #pragma unroll
            for (int mf = 0; mf < 4; mf++) {
                uint32_t addr = sA + (uint32_t)((aRow + mf * 16) * 128
                              + (((ks * 2 + aCHi) ^ aXor) * 16));
                LDSM_X4(a[mf], addr);
            }
            uint32_t b[4][2];
            #pragma unroll
            for (int g = 0; g < 2; g++) {
                uint32_t r[4];
                uint32_t addr = sB + (uint32_t)((bRow + g * 16) * 128
                              + (((ks * 2 + bCHi) ^ bXor) * 16));
                LDSM_X4(r, addr);
                b[2*g][0] = r[0]; b[2*g][1] = r[1];
                b[2*g+1][0] = r[2]; b[2*g+1][1] = r[3];
            }
            #pragma unroll
            for (int mf = 0; mf < 4; mf++)
                #pragma unroll
                for (int nf = 0; nf < 4; nf++)
                    MMA_F16(acc[mf][nf], a[mf], b[nf][0], b[nf][1]);
        }
    }

    // epilogue
    int mrow = bm + wm + (lane >> 2);
    int ncol = bn + wn + (lane & 3) * 2;
    #pragma unroll
    for (int mf = 0; mf < 4; mf++) {
        int r0 = mrow + mf * 16;
        #pragma unroll
        for (int nf = 0; nf < 4; nf++) {
            int n = ncol + nf * 8;
            float bz0 = bias[n], bz1 = bias[n + 1];
            float v0 = acc[mf][nf][0] + bz0;
            float v1 = acc[mf][nf][1] + bz1;
            float v2 = acc[mf][nf][2] + bz0;
            float v3 = acc[mf][nf][3] + bz1;
            size_t p0 = (size_t)r0 * N + n;
            size_t p1 = (size_t)(r0 + 8) * N + n;
            if (EPI == 0) {
                float2 a0 = *reinterpret_cast<const float2*>(aux + p0);
                float2 a1 = *reinterpret_cast<const float2*>(aux + p1);
                v0 = a0.x * (1.f / (1.f + __expf(-v0)));
                v1 = a0.y * (1.f / (1.f + __expf(-v1)));
                v2 = a1.x * (1.f / (1.f + __expf(-v2)));
                v3 = a1.y * (1.f / (1.f + __expf(-v3)));
                float2 o0; o0.x = v0; o0.y = v1;
                float2 o1; o1.x = v2; o1.y = v3;
                *reinterpret_cast<float2*>(outF + p0) = o0;
                *reinterpret_cast<float2*>(outF + p1) = o1;
            } else if (EPI == 1) {
                __half2 h0, h1;
                h0.x = __float2half(fmaxf(v0, 0.f));
                h0.y = __float2half(fmaxf(v1, 0.f));
                h1.x = __float2half(fmaxf(v2, 0.f));
                h1.y = __float2half(fmaxf(v3, 0.f));
                *reinterpret_cast<__half2*>(outH + p0) = h0;
                *reinterpret_cast<__half2*>(outH + p1) = h1;
            } else {
                float2 a0 = *reinterpret_cast<const float2*>(aux + p0);
                float2 a1 = *reinterpret_cast<const float2*>(aux + p1);
                float2 o0; o0.x = v0 + a0.x; o0.y = v1 + a0.y;
                float2 o1; o1.x = v2 + a1.x; o1.y = v3 + a1.y;
                *reinterpret_cast<float2*>(outF + p0) = o0;
                *reinterpret_cast<float2*>(outF + p1) = o1;
            }
        }
    }
}

// ---------------- host ----------------
extern "C" void kernel_launch(void* const* d_in, const int* in_sizes, int n_in,
                              void* d_out, int out_size)
{
    const float* x   = (const float*)d_in[0];
    const float* n1w = (const float*)d_in[1];
    const float* w1  = (const float*)d_in[2];
    const float* b1  = (const float*)d_in[3];
    const float* n2w = (const float*)d_in[4];
    const float* w2a = (const float*)d_in[5];
    const float* b2a = (const float*)d_in[6];
    const float* w2b = (const float*)d_in[7];
    const float* b2b = (const float*)d_in[8];
    float* out = (float*)d_out;

    void *p_s, *p_h, *p_a, *p_w1, *p_w2a, *p_w2b;
    float *out1;
    cudaGetSymbolAddress(&p_s, g_s);
    cudaGetSymbolAddress(&p_h, g_h);
    cudaGetSymbolAddress(&p_a, g_act);
    cudaGetSymbolAddress(&p_w1, g_w1T);
    cudaGetSymbolAddress(&p_w2a, g_w2aT);
    cudaGetSymbolAddress(&p_w2b, g_w2bT);
    cudaGetSymbolAddress((void**)&out1, g_out1);

    cudaFuncSetAttribute(mma_gemm<0>, cudaFuncAttributeMaxDynamicSharedMemorySize, SMTOT);
    cudaFuncSetAttribute(mma_gemm<1>, cudaFuncAttributeMaxDynamicSharedMemorySize, SMTOT);
    cudaFuncSetAttribute(mma_gemm<2>, cudaFuncAttributeMaxDynamicSharedMemorySize, SMTOT);

    // 1) fused: y = rmsnorm(x) (fp16) + transpose(w1, w2a, w2b) -> fp16 [N,K]
    prep_kernel<<<Mtot + TW1 + TW2A + TW2B, 256>>>(x, n1w, w1, w2a, w2b);

    // 2) state = cumsum(y)/scaler -> fp16
    scan_partial<<<dim3(Bsz, NCHUNK, 2), 256>>>();
    scan_prefix <<<dim3(Bsz, 2),         256>>>();
    scan_final  <<<dim3(Bsz, NCHUNK, 2), 256>>>();

    // 3) out1 = sigmoid(state @ w1 + b1) * x
    mma_gemm<0><<<dim3(Cdim / BNt, Mtot / BMt), 512, SMTOT>>>(
        (f16*)p_s, (f16*)p_w1, b1, x, out1, nullptr, Cdim, Cdim);

    // 4) h = rmsnorm(out1) -> fp16
    rmsnorm_h_kernel<<<Mtot, 256>>>(out1, n2w, (f16*)p_h);

    // 5) act = relu(h @ w2a + b2a) -> fp16
    mma_gemm<1><<<dim3(Edim / BNt, Mtot / BMt), 512, SMTOT>>>(
        (f16*)p_h, (f16*)p_w2a, b2a, nullptr, nullptr, (f16*)p_a, Edim, Cdim);

    // 6) out = act @ w2b + b2b + out1
    mma_gemm<2><<<dim3(Cdim / BNt, Mtot / BMt), 512, SMTOT>>>(
        (f16*)p_a, (f16*)p_w2b, b2b, out1, out, nullptr, Cdim, Edim);
}

// round 8
// speedup vs baseline: 1.2013x; 1.2013x over previous
#include <cuda_runtime.h>
#include <cuda.h>
#include <cuda_fp16.h>
#include <math.h>
#include <stdint.h>

#define Bsz   8
#define Tlen  2048
#define Cdim  1024
#define Edim  4096
#define Mtot  (Bsz * Tlen)       // 16384 tokens
#define CHUNK 32
#define NCHUNK (Tlen / CHUNK)    // 64

typedef __half f16;

// ---------------- scratch (no cudaMalloc allowed) ----------------
__device__ __align__(16) f16   g_y   [(size_t)Mtot * Cdim];   // rmsnorm1 out (fp16)
__device__ __align__(16) f16   g_out1[(size_t)Mtot * Cdim];   // gate*x (fp16 residual)
__device__ __align__(16) float g_csum[Bsz * NCHUNK * Cdim];

__device__ __align__(16) f16 g_s  [(size_t)Mtot * Cdim];   // state (fp16)
__device__ __align__(16) f16 g_h  [(size_t)Mtot * Cdim];   // rmsnorm2 out (fp16)
__device__ __align__(16) f16 g_act[(size_t)Mtot * Edim];   // relu hidden (fp16)

// transposed weights: [N, K] K-major fp16
__device__ __align__(16) f16 g_w1T [Cdim * Cdim];
__device__ __align__(16) f16 g_w2aT[(size_t)Edim * Cdim];
__device__ __align__(16) f16 g_w2bT[(size_t)Cdim * Edim];

// ---------------- helpers ----------------
__device__ __forceinline__ uint32_t smem_u32(const void* p) {
    uint32_t a;
    asm("{ .reg .u64 t; cvta.to.shared.u64 t, %1; cvt.u32.u64 %0, t; }" : "=r"(a) : "l"(p));
    return a;
}
__device__ __forceinline__ void cp16(uint32_t s, const void* g) {
    asm volatile("cp.async.cg.shared.global [%0], [%1], 16;" :: "r"(s), "l"(g) : "memory");
}
#define CP_COMMIT() asm volatile("cp.async.commit_group;" ::: "memory")
#define CP_WAIT(n)  asm volatile("cp.async.wait_group %0;" :: "n"(n) : "memory")

#define LDSM_X4(r, addr) \
    asm volatile("ldmatrix.sync.aligned.m8n8.x4.shared.b16 {%0,%1,%2,%3}, [%4];" \
        : "=r"((r)[0]), "=r"((r)[1]), "=r"((r)[2]), "=r"((r)[3]) : "r"(addr))

#define MMA_F16(d, a, b0, b1) \
    asm volatile("mma.sync.aligned.m16n8k16.row.col.f32.f16.f16.f32 " \
        "{%0,%1,%2,%3}, {%4,%5,%6,%7}, {%8,%9}, {%0,%1,%2,%3};" \
        : "+f"((d)[0]), "+f"((d)[1]), "+f"((d)[2]), "+f"((d)[3]) \
        : "r"((a)[0]), "r"((a)[1]), "r"((a)[2]), "r"((a)[3]), "r"(b0), "r"(b1))

// ---------------- fused prep: rmsnorm1 (fp16 out) + 3 weight transposes ----------------
__device__ __forceinline__ void rmsnorm_row_h(const float* __restrict__ x,
                                              const float* __restrict__ w,
                                              f16* __restrict__ y,
                                              int row, float* sh)
{
    const float4* xr = reinterpret_cast<const float4*>(x) + (size_t)row * (Cdim / 4);
    float4 v = xr[threadIdx.x];
    float ss = v.x * v.x + v.y * v.y + v.z * v.z + v.w * v.w;
    #pragma unroll
    for (int o = 16; o; o >>= 1) ss += __shfl_xor_sync(0xffffffffu, ss, o);
    int wid = threadIdx.x >> 5, lid = threadIdx.x & 31;
    if (lid == 0) sh[wid] = ss;
    __syncthreads();
    if (threadIdx.x < 8) {
        float t = sh[threadIdx.x];
        t += __shfl_xor_sync(0xffu, t, 1);
        t += __shfl_xor_sync(0xffu, t, 2);
        t += __shfl_xor_sync(0xffu, t, 4);
        if (threadIdx.x == 0) sh[0] = t;
    }
    __syncthreads();
    float inv = rsqrtf(sh[0] * (1.0f / Cdim) + 1e-6f);
    float4 wv = reinterpret_cast<const float4*>(w)[threadIdx.x];
    __half2 p0, p1;
    p0.x = __float2half(v.x * inv * wv.x);
    p0.y = __float2half(v.y * inv * wv.y);
    p1.x = __float2half(v.z * inv * wv.z);
    p1.y = __float2half(v.w * inv * wv.w);
    size_t base = (size_t)row * Cdim + threadIdx.x * 4;
    *reinterpret_cast<__half2*>(y + base)     = p0;
    *reinterpret_cast<__half2*>(y + base + 2) = p1;
}

__device__ __forceinline__ void transpose_tile(const float* __restrict__ in,
                                               f16* __restrict__ o16,
                                               int K, int N, int bx, int by, float* sh)
{
    int k0 = bx * 32, n0 = by * 32;
    int x = threadIdx.x & 31, y = threadIdx.x >> 5;
    #pragma unroll
    for (int i = y; i < 32; i += 8)
        sh[i * 33 + x] = in[(size_t)(k0 + i) * N + n0 + x];
    __syncthreads();
    #pragma unroll
    for (int i = y; i < 32; i += 8)
        o16[(size_t)(n0 + i) * K + k0 + x] = __float2half(sh[x * 33 + i]);
}

#define TW1  (Cdim / 32) * (Cdim / 32)   // 1024
#define TW2A (Cdim / 32) * (Edim / 32)   // 4096
#define TW2B (Edim / 32) * (Cdim / 32)   // 4096

__global__ void __launch_bounds__(256) prep_kernel(const float* __restrict__ x,
                                                   const float* __restrict__ n1w,
                                                   const float* __restrict__ w1,
                                                   const float* __restrict__ w2a,
                                                   const float* __restrict__ w2b)
{
    __shared__ float sh[32 * 33];
    int bid = blockIdx.x;
    if (bid < Mtot) { rmsnorm_row_h(x, n1w, g_y, bid, sh); return; }
    bid -= Mtot;
    if (bid < TW1)  { transpose_tile(w1,  g_w1T,  Cdim, Cdim, bid & 31, bid >> 5, sh); return; }
    bid -= TW1;
    if (bid < TW2A) { transpose_tile(w2a, g_w2aT, Cdim, Edim, bid & 31, bid >> 5, sh); return; }
    bid -= TW2A;
    transpose_tile(w2b, g_w2bT, Edim, Cdim, bid & 127, bid >> 7, sh);
}

// ---------------- rmsnorm over fp16 input -> fp16 (h = rmsnorm(out1)) ----------------
__global__ void __launch_bounds__(256) rmsnorm_h_kernel(const f16* __restrict__ x,
                                                        const float* __restrict__ w,
                                                        f16* __restrict__ yH)
{
    __shared__ float sh[8];
    int row = blockIdx.x;
    // 4 halves per thread (half2 x2)
    size_t base = (size_t)row * Cdim + threadIdx.x * 4;
    __half2 q0 = *reinterpret_cast<const __half2*>(x + base);
    __half2 q1 = *reinterpret_cast<const __half2*>(x + base + 2);
    float2 f0 = __half22float2(q0);
    float2 f1 = __half22float2(q1);
    float ss = f0.x * f0.x + f0.y * f0.y + f1.x * f1.x + f1.y * f1.y;
    #pragma unroll
    for (int o = 16; o; o >>= 1) ss += __shfl_xor_sync(0xffffffffu, ss, o);
    int wid = threadIdx.x >> 5, lid = threadIdx.x & 31;
    if (lid == 0) sh[wid] = ss;
    __syncthreads();
    if (threadIdx.x < 8) {
        float t = sh[threadIdx.x];
        t += __shfl_xor_sync(0xffu, t, 1);
        t += __shfl_xor_sync(0xffu, t, 2);
        t += __shfl_xor_sync(0xffu, t, 4);
        if (threadIdx.x == 0) sh[0] = t;
    }
    __syncthreads();
    float inv = rsqrtf(sh[0] * (1.0f / Cdim) + 1e-6f);
    float4 wv = reinterpret_cast<const float4*>(w)[threadIdx.x];
    __half2 p0, p1;
    p0.x = __float2half(f0.x * inv * wv.x);
    p0.y = __float2half(f0.y * inv * wv.y);
    p1.x = __float2half(f1.x * inv * wv.z);
    p1.y = __float2half(f1.y * inv * wv.w);
    *reinterpret_cast<__half2*>(yH + base)     = p0;
    *reinterpret_cast<__half2*>(yH + base + 2) = p1;
}

// ---------------- chunked scan (fp16 input, fp32 accumulate, 2 channels/thread) ----------------
#define C2 (Cdim / 2)

__global__ void __launch_bounds__(256) scan_partial()
{
    int b = blockIdx.x, ch = blockIdx.y;
    int c2 = blockIdx.z * 256 + threadIdx.x;
    const __half2* p = reinterpret_cast<const __half2*>(g_y)
                     + (size_t)(b * Tlen + ch * CHUNK) * C2 + c2;
    float2 s = make_float2(0.f, 0.f);
    #pragma unroll
    for (int t = 0; t < CHUNK; t++) {
        float2 v = __half22float2(p[(size_t)t * C2]);
        s.x += v.x; s.y += v.y;
    }
    reinterpret_cast<float2*>(g_csum)[(b * NCHUNK + ch) * C2 + c2] = s;
}

__global__ void __launch_bounds__(256) scan_prefix()
{
    int b = blockIdx.x;
    int c2 = blockIdx.y * 256 + threadIdx.x;
    float2* buf = reinterpret_cast<float2*>(g_csum);
    float2 run = make_float2(0.f, 0.f);
    #pragma unroll
    for (int ch = 0; ch < NCHUNK; ch++) {
        int idx = (b * NCHUNK + ch) * C2 + c2;
        float2 v = buf[idx];
        buf[idx] = run;
        run.x += v.x; run.y += v.y;
    }
}

__global__ void __launch_bounds__(256) scan_final()
{
    int b = blockIdx.x, ch = blockIdx.y;
    int c2 = blockIdx.z * 256 + threadIdx.x;
    float2 run = reinterpret_cast<const float2*>(g_csum)[(b * NCHUNK + ch) * C2 + c2];
    const __half2* p = reinterpret_cast<const __half2*>(g_y)
                     + (size_t)(b * Tlen + ch * CHUNK) * C2 + c2;
    __half2* o = reinterpret_cast<__half2*>(g_s)
               + (size_t)(b * Tlen + ch * CHUNK) * C2 + c2;
    int tg0 = ch * CHUNK;
    #pragma unroll
    for (int t = 0; t < CHUNK; t++) {
        float2 v = __half22float2(p[(size_t)t * C2]);
        run.x += v.x; run.y += v.y;
        float tg = (float)(tg0 + t);
        float rs = 1.0f / (0.5f * (tg + 1.f) * (tg + 2.f));
        __half2 hv;
        hv.x = __float2half(run.x * rs);
        hv.y = __float2half(run.y * rs);
        o[(size_t)t * C2] = hv;
    }
}

// ---------------- fp16 HMMA GEMM: 128x128x64 tiles, 3-stage cp.async ----------------
// A: [M,K] row-major f16, B: [N,K] row-major f16 -> C[M,N]
// EPI 0: outH1 = (f16)(sigmoid(acc+bias) * auxF)           (gate * x, fp16 out)
// EPI 1: outH = (f16) relu(acc+bias)
// EPI 2: outF = acc + bias + auxH (fp16 residual)
#define BKt    64
#define STG    3
#define TILEB  32768                // A 16KB + B 16KB per stage
#define SMTOT  (STG * TILEB)

__device__ __forceinline__ void load_tile64(const f16* __restrict__ A,
                                            const f16* __restrict__ B,
                                            int bm, int bn, int koff, int K,
                                            uint32_t sbase, int stage, int tid)
{
    uint32_t sA = sbase + stage * TILEB;
    uint32_t sB = sA + 16384;
    #pragma unroll
    for (int i = 0; i < 4; i++) {
        int idx = tid + i * 256;          // 0..1023
        int row = idx >> 3, ch = idx & 7;
        int chs = ch ^ (row & 7);         // 128B-row swizzle
        uint32_t so = (uint32_t)(row * 128 + chs * 16);
        cp16(sA + so, A + (size_t)(bm + row) * K + koff + ch * 8);
        cp16(sB + so, B + (size_t)(bn + row) * K + koff + ch * 8);
    }
}

template<int EPI>
__global__ void __launch_bounds__(256, 2) mma_gemm(
    const f16* __restrict__ Ag, const f16* __restrict__ Bg,
    const float* __restrict__ bias,
    const float* __restrict__ auxF, const f16* __restrict__ auxH,
    float* __restrict__ outF, f16* __restrict__ outH,
    int N, int K)
{
    extern __shared__ __align__(16) char smem[];
    uint32_t sbase = smem_u32(smem);
    int tid = threadIdx.x, wid = tid >> 5, lane = tid & 31;
    int bm = blockIdx.y * 128, bn = blockIdx.x * 128;
    int wm = (wid >> 2) * 64, wn = (wid & 3) * 32;

    int nkt = K / BKt;

    float acc[4][4][4] = {};

    // prologue: prefetch 2 tiles
    load_tile64(Ag, Bg, bm, bn, 0,   K, sbase, 0, tid); CP_COMMIT();
    load_tile64(Ag, Bg, bm, bn, BKt, K, sbase, 1, tid); CP_COMMIT();

    // ldmatrix lane constants
    int l8 = lane & 7;
    int aRow  = wm + l8 + ((lane >> 3) & 1) * 8;   // + mf*16
    int aCHi  = (lane >> 4) & 1;
    int aXor  = aRow & 7;
    int bRow  = wn + l8 + ((lane >> 4) & 1) * 8;   // + g*16
    int bCHi  = (lane >> 3) & 1;
    int bXor  = bRow & 7;

    int cs = 0, ls = 2;   // compute stage, load stage
    for (int kk = 0; kk < nkt; kk++) {
        if (kk + 1 < nkt) { CP_WAIT(1); } else { CP_WAIT(0); }
        __syncthreads();

        if (kk + 2 < nkt) {
            load_tile64(Ag, Bg, bm, bn, (kk + 2) * BKt, K, sbase, ls, tid);
            CP_COMMIT();
            if (++ls == STG) ls = 0;
        }

        uint32_t sA = sbase + cs * TILEB;
        uint32_t sB = sA + 16384;
        if (++cs == STG) cs = 0;

        #pragma unroll
        for (int ks = 0; ks < 4; ks++) {
            uint32_t a[4][4];
            #pragma unroll
            for (int mf = 0; mf < 4; mf++) {
                uint32_t addr = sA + (uint32_t)((aRow + mf * 16) * 128
                              + (((ks * 2 + aCHi) ^ aXor) * 16));
                LDSM_X4(a[mf], addr);
            }
            uint32_t b[4][2];
            #pragma unroll
            for (int g = 0; g < 2; g++) {
                uint32_t r[4];
                uint32_t addr = sB + (uint32_t)((bRow + g * 16) * 128
                              + (((ks * 2 + bCHi) ^ bXor) * 16));
                LDSM_X4(r, addr);
                b[2*g][0] = r[0]; b[2*g][1] = r[1];
                b[2*g+1][0] = r[2]; b[2*g+1][1] = r[3];
            }
            #pragma unroll
            for (int mf = 0; mf < 4; mf++)
                #pragma unroll
                for (int nf = 0; nf < 4; nf++)
                    MMA_F16(acc[mf][nf], a[mf], b[nf][0], b[nf][1]);
        }
    }

    // epilogue
    int mrow = bm + wm + (lane >> 2);
    int ncol = bn + wn + (lane & 3) * 2;
    #pragma unroll
    for (int mf = 0; mf < 4; mf++) {
        int r0 = mrow + mf * 16;
        #pragma unroll
        for (int nf = 0; nf < 4; nf++) {
            int n = ncol + nf * 8;
            float bz0 = bias[n], bz1 = bias[n + 1];
            float v0 = acc[mf][nf][0] + bz0;
            float v1 = acc[mf][nf][1] + bz1;
            float v2 = acc[mf][nf][2] + bz0;
            float v3 = acc[mf][nf][3] + bz1;
            size_t p0 = (size_t)r0 * N + n;
            size_t p1 = (size_t)(r0 + 8) * N + n;
            if (EPI == 0) {
                float2 a0 = *reinterpret_cast<const float2*>(auxF + p0);
                float2 a1 = *reinterpret_cast<const float2*>(auxF + p1);
                v0 = a0.x * (1.f / (1.f + __expf(-v0)));
                v1 = a0.y * (1.f / (1.f + __expf(-v1)));
                v2 = a1.x * (1.f / (1.f + __expf(-v2)));
                v3 = a1.y * (1.f / (1.f + __expf(-v3)));
                __half2 h0, h1;
                h0.x = __float2half(v0); h0.y = __float2half(v1);
                h1.x = __float2half(v2); h1.y = __float2half(v3);
                *reinterpret_cast<__half2*>(outH + p0) = h0;
                *reinterpret_cast<__half2*>(outH + p1) = h1;
            } else if (EPI == 1) {
                __half2 h0, h1;
                h0.x = __float2half(fmaxf(v0, 0.f));
                h0.y = __float2half(fmaxf(v1, 0.f));
                h1.x = __float2half(fmaxf(v2, 0.f));
                h1.y = __float2half(fmaxf(v3, 0.f));
                *reinterpret_cast<__half2*>(outH + p0) = h0;
                *reinterpret_cast<__half2*>(outH + p1) = h1;
            } else {
                float2 a0 = __half22float2(*reinterpret_cast<const __half2*>(auxH + p0));
                float2 a1 = __half22float2(*reinterpret_cast<const __half2*>(auxH + p1));
                float2 o0; o0.x = v0 + a0.x; o0.y = v1 + a0.y;
                float2 o1; o1.x = v2 + a1.x; o1.y = v3 + a1.y;
                *reinterpret_cast<float2*>(outF + p0) = o0;
                *reinterpret_cast<float2*>(outF + p1) = o1;
            }
        }
    }
}

// ---------------- host ----------------
extern "C" void kernel_launch(void* const* d_in, const int* in_sizes, int n_in,
                              void* d_out, int out_size)
{
    const float* x   = (const float*)d_in[0];
    const float* n1w = (const float*)d_in[1];
    const float* w1  = (const float*)d_in[2];
    const float* b1  = (const float*)d_in[3];
    const float* n2w = (const float*)d_in[4];
    const float* w2a = (const float*)d_in[5];
    const float* b2a = (const float*)d_in[6];
    const float* w2b = (const float*)d_in[7];
    const float* b2b = (const float*)d_in[8];
    float* out = (float*)d_out;

    void *p_s, *p_h, *p_a, *p_w1, *p_w2a, *p_w2b, *p_o1;
    cudaGetSymbolAddress(&p_s, g_s);
    cudaGetSymbolAddress(&p_h, g_h);
    cudaGetSymbolAddress(&p_a, g_act);
    cudaGetSymbolAddress(&p_w1, g_w1T);
    cudaGetSymbolAddress(&p_w2a, g_w2aT);
    cudaGetSymbolAddress(&p_w2b, g_w2bT);
    cudaGetSymbolAddress(&p_o1, g_out1);

    cudaFuncSetAttribute(mma_gemm<0>, cudaFuncAttributeMaxDynamicSharedMemorySize, SMTOT);
    cudaFuncSetAttribute(mma_gemm<1>, cudaFuncAttributeMaxDynamicSharedMemorySize, SMTOT);
    cudaFuncSetAttribute(mma_gemm<2>, cudaFuncAttributeMaxDynamicSharedMemorySize, SMTOT);

    // 1) fused: y = rmsnorm(x) (fp16) + transpose(w1, w2a, w2b) -> fp16 [N,K]
    prep_kernel<<<Mtot + TW1 + TW2A + TW2B, 256>>>(x, n1w, w1, w2a, w2b);

    // 2) state = cumsum(y)/scaler -> fp16
    scan_partial<<<dim3(Bsz, NCHUNK, 2), 256>>>();
    scan_prefix <<<dim3(Bsz, 2),         256>>>();
    scan_final  <<<dim3(Bsz, NCHUNK, 2), 256>>>();

    // 3) out1 = (f16) sigmoid(state @ w1 + b1) * x
    mma_gemm<0><<<dim3(Cdim / 128, Mtot / 128), 256, SMTOT>>>(
        (f16*)p_s, (f16*)p_w1, b1, x, nullptr, nullptr, (f16*)p_o1, Cdim, Cdim);

    // 4) h = rmsnorm(out1) -> fp16
    rmsnorm_h_kernel<<<Mtot, 256>>>((f16*)p_o1, n2w, (f16*)p_h);

    // 5) act = relu(h @ w2a + b2a) -> fp16
    mma_gemm<1><<<dim3(Edim / 128, Mtot / 128), 256, SMTOT>>>(
        (f16*)p_h, (f16*)p_w2a, b2a, nullptr, nullptr, nullptr, (f16*)p_a, Edim, Cdim);

    // 6) out = act @ w2b + b2b + out1
    mma_gemm<2><<<dim3(Cdim / 128, Mtot / 128), 256, SMTOT>>>(
        (f16*)p_a, (f16*)p_w2b, b2b, nullptr, (f16*)p_o1, out, nullptr, Cdim, Edim);
}

// round 9
// speedup vs baseline: 1.2140x; 1.0106x over previous
#include <cuda_runtime.h>
#include <cuda.h>
#include <cuda_fp16.h>
#include <math.h>
#include <stdint.h>

#define Bsz   8
#define Tlen  2048
#define Cdim  1024
#define Edim  4096
#define Mtot  (Bsz * Tlen)       // 16384 tokens
#define CHUNK 32
#define NCHUNK (Tlen / CHUNK)    // 64

typedef __half f16;

// ---------------- scratch (no cudaMalloc allowed) ----------------
__device__ __align__(16) f16   g_y   [(size_t)Mtot * Cdim];   // rmsnorm1 out (fp16)
__device__ __align__(16) f16   g_out1[(size_t)Mtot * Cdim];   // gate*x (fp16 residual)
__device__ __align__(16) float g_csum[Bsz * NCHUNK * Cdim];
__device__ __align__(16) float g_inv [Mtot];                  // 1/rms of out1 rows

__device__ __align__(16) f16 g_s  [(size_t)Mtot * Cdim];   // state (fp16)
__device__ __align__(16) f16 g_act[(size_t)Mtot * Edim];   // relu hidden (fp16)

// transposed weights: [N, K] K-major fp16
__device__ __align__(16) f16 g_w1T [Cdim * Cdim];
__device__ __align__(16) f16 g_w2aT[(size_t)Edim * Cdim];  // includes n2w fold
__device__ __align__(16) f16 g_w2bT[(size_t)Cdim * Edim];

// ---------------- helpers ----------------
__device__ __forceinline__ uint32_t smem_u32(const void* p) {
    uint32_t a;
    asm("{ .reg .u64 t; cvta.to.shared.u64 t, %1; cvt.u32.u64 %0, t; }" : "=r"(a) : "l"(p));
    return a;
}
__device__ __forceinline__ void cp16(uint32_t s, const void* g) {
    asm volatile("cp.async.cg.shared.global [%0], [%1], 16;" :: "r"(s), "l"(g) : "memory");
}
#define CP_COMMIT() asm volatile("cp.async.commit_group;" ::: "memory")
#define CP_WAIT(n)  asm volatile("cp.async.wait_group %0;" :: "n"(n) : "memory")

#define LDSM_X4(r, addr) \
    asm volatile("ldmatrix.sync.aligned.m8n8.x4.shared.b16 {%0,%1,%2,%3}, [%4];" \
        : "=r"((r)[0]), "=r"((r)[1]), "=r"((r)[2]), "=r"((r)[3]) : "r"(addr))

#define MMA_F16(d, a, b0, b1) \
    asm volatile("mma.sync.aligned.m16n8k16.row.col.f32.f16.f16.f32 " \
        "{%0,%1,%2,%3}, {%4,%5,%6,%7}, {%8,%9}, {%0,%1,%2,%3};" \
        : "+f"((d)[0]), "+f"((d)[1]), "+f"((d)[2]), "+f"((d)[3]) \
        : "r"((a)[0]), "r"((a)[1]), "r"((a)[2]), "r"((a)[3]), "r"(b0), "r"(b1))

// ---------------- rmsnorm1: x fp32 -> y fp16 ----------------
__global__ void __launch_bounds__(256) rms1_kernel(const float* __restrict__ x,
                                                   const float* __restrict__ w)
{
    __shared__ float sh[8];
    int row = blockIdx.x;
    const float4* xr = reinterpret_cast<const float4*>(x) + (size_t)row * (Cdim / 4);
    float4 v = xr[threadIdx.x];
    float ss = v.x * v.x + v.y * v.y + v.z * v.z + v.w * v.w;
    #pragma unroll
    for (int o = 16; o; o >>= 1) ss += __shfl_xor_sync(0xffffffffu, ss, o);
    int wid = threadIdx.x >> 5, lid = threadIdx.x & 31;
    if (lid == 0) sh[wid] = ss;
    __syncthreads();
    if (threadIdx.x < 8) {
        float t = sh[threadIdx.x];
        t += __shfl_xor_sync(0xffu, t, 1);
        t += __shfl_xor_sync(0xffu, t, 2);
        t += __shfl_xor_sync(0xffu, t, 4);
        if (threadIdx.x == 0) sh[0] = t;
    }
    __syncthreads();
    float inv = rsqrtf(sh[0] * (1.0f / Cdim) + 1e-6f);
    float4 wv = reinterpret_cast<const float4*>(w)[threadIdx.x];
    __half2 p0, p1;
    p0.x = __float2half(v.x * inv * wv.x);
    p0.y = __float2half(v.y * inv * wv.y);
    p1.x = __float2half(v.z * inv * wv.z);
    p1.y = __float2half(v.w * inv * wv.w);
    size_t base = (size_t)row * Cdim + threadIdx.x * 4;
    *reinterpret_cast<__half2*>(g_y + base)     = p0;
    *reinterpret_cast<__half2*>(g_y + base + 2) = p1;
}

// ---------------- weight transposes (side stream) ----------------
__device__ __forceinline__ void transpose_tile(const float* __restrict__ in,
                                               f16* __restrict__ o16,
                                               const float* __restrict__ scale,
                                               int K, int N, int bx, int by, float* sh)
{
    int k0 = bx * 32, n0 = by * 32;
    int x = threadIdx.x & 31, y = threadIdx.x >> 5;
    #pragma unroll
    for (int i = y; i < 32; i += 8)
        sh[i * 33 + x] = in[(size_t)(k0 + i) * N + n0 + x];
    __syncthreads();
    float sc = scale ? scale[k0 + x] : 1.0f;
    #pragma unroll
    for (int i = y; i < 32; i += 8)
        o16[(size_t)(n0 + i) * K + k0 + x] = __float2half(sh[x * 33 + i] * sc);
}

#define TW1  (Cdim / 32) * (Cdim / 32)   // 1024
#define TW2A (Cdim / 32) * (Edim / 32)   // 4096
#define TW2B (Edim / 32) * (Cdim / 32)   // 4096

__global__ void __launch_bounds__(256) trans_kernel(const float* __restrict__ w1,
                                                    const float* __restrict__ w2a,
                                                    const float* __restrict__ n2w,
                                                    const float* __restrict__ w2b)
{
    __shared__ float sh[32 * 33];
    int bid = blockIdx.x;
    if (bid < TW1)  { transpose_tile(w1,  g_w1T,  nullptr, Cdim, Cdim, bid & 31, bid >> 5, sh); return; }
    bid -= TW1;
    if (bid < TW2A) { transpose_tile(w2a, g_w2aT, n2w, Cdim, Edim, bid & 31, bid >> 5, sh); return; }
    bid -= TW2A;
    transpose_tile(w2b, g_w2bT, nullptr, Edim, Cdim, bid & 127, bid >> 7, sh);
}

// ---------------- row inv-rms of out1 (1 warp per row) ----------------
__global__ void __launch_bounds__(256) row_inv_kernel()
{
    int row  = blockIdx.x * 8 + (threadIdx.x >> 5);
    int lane = threadIdx.x & 31;
    const uint4* p = reinterpret_cast<const uint4*>(g_out1 + (size_t)row * Cdim);
    float ss = 0.f;
    #pragma unroll
    for (int i = 0; i < 4; i++) {
        uint4 q = p[lane + i * 32];
        const __half2* h = reinterpret_cast<const __half2*>(&q);
        #pragma unroll
        for (int j = 0; j < 4; j++) {
            float2 f = __half22float2(h[j]);
            ss += f.x * f.x + f.y * f.y;
        }
    }
    #pragma unroll
    for (int o = 16; o; o >>= 1) ss += __shfl_xor_sync(0xffffffffu, ss, o);
    if (lane == 0) g_inv[row] = rsqrtf(ss * (1.0f / Cdim) + 1e-6f);
}

// ---------------- chunked scan (fp16 input, fp32 accumulate, 2 channels/thread) ----------------
#define C2 (Cdim / 2)

__global__ void __launch_bounds__(256) scan_partial()
{
    int b = blockIdx.x, ch = blockIdx.y;
    int c2 = blockIdx.z * 256 + threadIdx.x;
    const __half2* p = reinterpret_cast<const __half2*>(g_y)
                     + (size_t)(b * Tlen + ch * CHUNK) * C2 + c2;
    float2 s = make_float2(0.f, 0.f);
    #pragma unroll
    for (int t = 0; t < CHUNK; t++) {
        float2 v = __half22float2(p[(size_t)t * C2]);
        s.x += v.x; s.y += v.y;
    }
    reinterpret_cast<float2*>(g_csum)[(b * NCHUNK + ch) * C2 + c2] = s;
}

__global__ void __launch_bounds__(256) scan_prefix()
{
    int b = blockIdx.x;
    int c2 = blockIdx.y * 256 + threadIdx.x;
    float2* buf = reinterpret_cast<float2*>(g_csum);
    float2 run = make_float2(0.f, 0.f);
    #pragma unroll
    for (int ch = 0; ch < NCHUNK; ch++) {
        int idx = (b * NCHUNK + ch) * C2 + c2;
        float2 v = buf[idx];
        buf[idx] = run;
        run.x += v.x; run.y += v.y;
    }
}

__global__ void __launch_bounds__(256) scan_final()
{
    int b = blockIdx.x, ch = blockIdx.y;
    int c2 = blockIdx.z * 256 + threadIdx.x;
    float2 run = reinterpret_cast<const float2*>(g_csum)[(b * NCHUNK + ch) * C2 + c2];
    const __half2* p = reinterpret_cast<const __half2*>(g_y)
                     + (size_t)(b * Tlen + ch * CHUNK) * C2 + c2;
    __half2* o = reinterpret_cast<__half2*>(g_s)
               + (size_t)(b * Tlen + ch * CHUNK) * C2 + c2;
    int tg0 = ch * CHUNK;
    #pragma unroll
    for (int t = 0; t < CHUNK; t++) {
        float2 v = __half22float2(p[(size_t)t * C2]);
        run.x += v.x; run.y += v.y;
        float tg = (float)(tg0 + t);
        float rs = 1.0f / (0.5f * (tg + 1.f) * (tg + 2.f));
        __half2 hv;
        hv.x = __float2half(run.x * rs);
        hv.y = __float2half(run.y * rs);
        o[(size_t)t * C2] = hv;
    }
}

// ---------------- fp16 HMMA GEMM: 128x128x64 tiles, 3-stage cp.async ----------------
// A: [M,K] row-major f16, B: [N,K] row-major f16 -> C[M,N]
// EPI 0: outH = (f16)(sigmoid(acc+bias) * auxF)          (gate * x)
// EPI 1: outH = (f16) relu(acc*rowinv[m] + bias)         (fused rmsnorm2 scale)
// EPI 2: outF = acc + bias + auxH (fp16 residual)
#define BKt    64
#define STG    3
#define TILEB  32768
#define SMTOT  (STG * TILEB)

__device__ __forceinline__ void load_tile64(const f16* __restrict__ A,
                                            const f16* __restrict__ B,
                                            int bm, int bn, int koff, int K,
                                            uint32_t sbase, int stage, int tid)
{
    uint32_t sA = sbase + stage * TILEB;
    uint32_t sB = sA + 16384;
    #pragma unroll
    for (int i = 0; i < 4; i++) {
        int idx = tid + i * 256;
        int row = idx >> 3, ch = idx & 7;
        int chs = ch ^ (row & 7);
        uint32_t so = (uint32_t)(row * 128 + chs * 16);
        cp16(sA + so, A + (size_t)(bm + row) * K + koff + ch * 8);
        cp16(sB + so, B + (size_t)(bn + row) * K + koff + ch * 8);
    }
}

template<int EPI>
__global__ void __launch_bounds__(256, 2) mma_gemm(
    const f16* __restrict__ Ag, const f16* __restrict__ Bg,
    const float* __restrict__ bias,
    const float* __restrict__ auxF, const f16* __restrict__ auxH,
    const float* __restrict__ rowinv,
    float* __restrict__ outF, f16* __restrict__ outH,
    int N, int K)
{
    extern __shared__ __align__(16) char smem[];
    uint32_t sbase = smem_u32(smem);
    int tid = threadIdx.x, wid = tid >> 5, lane = tid & 31;
    int bm = blockIdx.y * 128, bn = blockIdx.x * 128;
    int wm = (wid >> 2) * 64, wn = (wid & 3) * 32;

    int nkt = K / BKt;

    float acc[4][4][4] = {};

    load_tile64(Ag, Bg, bm, bn, 0,   K, sbase, 0, tid); CP_COMMIT();
    load_tile64(Ag, Bg, bm, bn, BKt, K, sbase, 1, tid); CP_COMMIT();

    int l8 = lane & 7;
    int aRow  = wm + l8 + ((lane >> 3) & 1) * 8;
    int aCHi  = (lane >> 4) & 1;
    int aXor  = aRow & 7;
    int bRow  = wn + l8 + ((lane >> 4) & 1) * 8;
    int bCHi  = (lane >> 3) & 1;
    int bXor  = bRow & 7;

    int cs = 0, ls = 2;
    for (int kk = 0; kk < nkt; kk++) {
        if (kk + 1 < nkt) { CP_WAIT(1); } else { CP_WAIT(0); }
        __syncthreads();

        if (kk + 2 < nkt) {
            load_tile64(Ag, Bg, bm, bn, (kk + 2) * BKt, K, sbase, ls, tid);
            CP_COMMIT();
            if (++ls == STG) ls = 0;
        }

        uint32_t sA = sbase + cs * TILEB;
        uint32_t sB = sA + 16384;
        if (++cs == STG) cs = 0;

        #pragma unroll
        for (int ks = 0; ks < 4; ks++) {
            uint32_t a[4][4];
            #pragma unroll
            for (int mf = 0; mf < 4; mf++) {
                uint32_t addr = sA + (uint32_t)((aRow + mf * 16) * 128
                              + (((ks * 2 + aCHi) ^ aXor) * 16));
                LDSM_X4(a[mf], addr);
            }
            uint32_t b[4][2];
            #pragma unroll
            for (int g = 0; g < 2; g++) {
                uint32_t r[4];
                uint32_t addr = sB + (uint32_t)((bRow + g * 16) * 128
                              + (((ks * 2 + bCHi) ^ bXor) * 16));
                LDSM_X4(r, addr);
                b[2*g][0] = r[0]; b[2*g][1] = r[1];
                b[2*g+1][0] = r[2]; b[2*g+1][1] = r[3];
            }
            #pragma unroll
            for (int mf = 0; mf < 4; mf++)
                #pragma unroll
                for (int nf = 0; nf < 4; nf++)
                    MMA_F16(acc[mf][nf], a[mf], b[nf][0], b[nf][1]);
        }
    }

    // epilogue
    int mrow = bm + wm + (lane >> 2);
    int ncol = bn + wn + (lane & 3) * 2;
    #pragma unroll
    for (int mf = 0; mf < 4; mf++) {
        int r0 = mrow + mf * 16;
        float iv0 = 1.f, iv1 = 1.f;
        if (EPI == 1) { iv0 = rowinv[r0]; iv1 = rowinv[r0 + 8]; }
        #pragma unroll
        for (int nf = 0; nf < 4; nf++) {
            int n = ncol + nf * 8;
            float bz0 = bias[n], bz1 = bias[n + 1];
            size_t p0 = (size_t)r0 * N + n;
            size_t p1 = (size_t)(r0 + 8) * N + n;
            if (EPI == 0) {
                float v0 = acc[mf][nf][0] + bz0;
                float v1 = acc[mf][nf][1] + bz1;
                float v2 = acc[mf][nf][2] + bz0;
                float v3 = acc[mf][nf][3] + bz1;
                float2 a0 = *reinterpret_cast<const float2*>(auxF + p0);
                float2 a1 = *reinterpret_cast<const float2*>(auxF + p1);
                v0 = a0.x * (1.f / (1.f + __expf(-v0)));
                v1 = a0.y * (1.f / (1.f + __expf(-v1)));
                v2 = a1.x * (1.f / (1.f + __expf(-v2)));
                v3 = a1.y * (1.f / (1.f + __expf(-v3)));
                __half2 h0, h1;
                h0.x = __float2half(v0); h0.y = __float2half(v1);
                h1.x = __float2half(v2); h1.y = __float2half(v3);
                *reinterpret_cast<__half2*>(outH + p0) = h0;
                *reinterpret_cast<__half2*>(outH + p1) = h1;
            } else if (EPI == 1) {
                __half2 h0, h1;
                h0.x = __float2half(fmaxf(acc[mf][nf][0] * iv0 + bz0, 0.f));
                h0.y = __float2half(fmaxf(acc[mf][nf][1] * iv0 + bz1, 0.f));
                h1.x = __float2half(fmaxf(acc[mf][nf][2] * iv1 + bz0, 0.f));
                h1.y = __float2half(fmaxf(acc[mf][nf][3] * iv1 + bz1, 0.f));
                *reinterpret_cast<__half2*>(outH + p0) = h0;
                *reinterpret_cast<__half2*>(outH + p1) = h1;
            } else {
                float2 a0 = __half22float2(*reinterpret_cast<const __half2*>(auxH + p0));
                float2 a1 = __half22float2(*reinterpret_cast<const __half2*>(auxH + p1));
                float2 o0; o0.x = acc[mf][nf][0] + bz0 + a0.x; o0.y = acc[mf][nf][1] + bz1 + a0.y;
                float2 o1; o1.x = acc[mf][nf][2] + bz0 + a1.x; o1.y = acc[mf][nf][3] + bz1 + a1.y;
                *reinterpret_cast<float2*>(outF + p0) = o0;
                *reinterpret_cast<float2*>(outF + p1) = o1;
            }
        }
    }
}

// ---------------- host ----------------
extern "C" void kernel_launch(void* const* d_in, const int* in_sizes, int n_in,
                              void* d_out, int out_size)
{
    const float* x   = (const float*)d_in[0];
    const float* n1w = (const float*)d_in[1];
    const float* w1  = (const float*)d_in[2];
    const float* b1  = (const float*)d_in[3];
    const float* n2w = (const float*)d_in[4];
    const float* w2a = (const float*)d_in[5];
    const float* b2a = (const float*)d_in[6];
    const float* w2b = (const float*)d_in[7];
    const float* b2b = (const float*)d_in[8];
    float* out = (float*)d_out;

    void *p_s, *p_a, *p_w1, *p_w2a, *p_w2b, *p_o1, *p_iv;
    cudaGetSymbolAddress(&p_s, g_s);
    cudaGetSymbolAddress(&p_a, g_act);
    cudaGetSymbolAddress(&p_w1, g_w1T);
    cudaGetSymbolAddress(&p_w2a, g_w2aT);
    cudaGetSymbolAddress(&p_w2b, g_w2bT);
    cudaGetSymbolAddress(&p_o1, g_out1);
    cudaGetSymbolAddress(&p_iv, g_inv);

    cudaFuncSetAttribute(mma_gemm<0>, cudaFuncAttributeMaxDynamicSharedMemorySize, SMTOT);
    cudaFuncSetAttribute(mma_gemm<1>, cudaFuncAttributeMaxDynamicSharedMemorySize, SMTOT);
    cudaFuncSetAttribute(mma_gemm<2>, cudaFuncAttributeMaxDynamicSharedMemorySize, SMTOT);

    // persistent side stream + events (created once; host resources only)
    static cudaStream_t s_side = nullptr;
    static cudaEvent_t ev_fork = nullptr, ev_join = nullptr;
    if (!s_side) {
        cudaStreamCreateWithFlags(&s_side, cudaStreamNonBlocking);
        cudaEventCreateWithFlags(&ev_fork, cudaEventDisableTiming);
        cudaEventCreateWithFlags(&ev_join, cudaEventDisableTiming);
    }

    // fork: weight transposes on side stream, overlapping rmsnorm+scan chain
    cudaEventRecord(ev_fork, 0);
    cudaStreamWaitEvent(s_side, ev_fork, 0);
    trans_kernel<<<TW1 + TW2A + TW2B, 256, 0, s_side>>>(w1, w2a, n2w, w2b);
    cudaEventRecord(ev_join, s_side);

    // main: y = rmsnorm(x) -> fp16; state = cumsum(y)/scaler -> fp16
    rms1_kernel<<<Mtot, 256>>>(x, n1w);
    scan_partial<<<dim3(Bsz, NCHUNK, 2), 256>>>();
    scan_prefix <<<dim3(Bsz, 2),         256>>>();
    scan_final  <<<dim3(Bsz, NCHUNK, 2), 256>>>();

    // join before first GEMM needs weights
    cudaStreamWaitEvent(0, ev_join, 0);

    // out1 = (f16) sigmoid(state @ w1 + b1) * x
    mma_gemm<0><<<dim3(Cdim / 128, Mtot / 128), 256, SMTOT>>>(
        (f16*)p_s, (f16*)p_w1, b1, x, nullptr, nullptr, nullptr, (f16*)p_o1, Cdim, Cdim);

    // per-row inv-rms of out1 (replaces rmsnorm2 kernel)
    row_inv_kernel<<<Mtot / 8, 256>>>();

    // act = relu((out1 @ (n2w⊙w2a)) * inv[m] + b2a) -> fp16
    mma_gemm<1><<<dim3(Edim / 128, Mtot / 128), 256, SMTOT>>>(
        (f16*)p_o1, (f16*)p_w2a, b2a, nullptr, nullptr, (const float*)p_iv,
        nullptr, (f16*)p_a, Edim, Cdim);

    // out = act @ w2b + b2b + out1
    mma_gemm<2><<<dim3(Cdim / 128, Mtot / 128), 256, SMTOT>>>(
        (f16*)p_a, (f16*)p_w2b, b2b, nullptr, (f16*)p_o1, nullptr,
        out, nullptr, Cdim, Edim);
}